// round 5
// baseline (speedup 1.0000x reference)
#include <cuda_runtime.h>
#include <math.h>

#define MDIM 512
#define LDIM 31
#define LPAD 32                  // padded lambda stride (bank/idx friendly)
#define CTOT 542                 // MDIM + LDIM - 1
#define NX   1024
#define ROWE (NX * LDIM)         // 31744 floats per input row strip
#define XCE  (MDIM * LDIM)       // 15872 floats per output row strip

#define WC     64                // output columns per tile
#define NTILE  (MDIM / WC)       // 8
#define WCOLS  (2 * WC + 2)      // 130 input cols per window
#define SROW_N (WCOLS * LPAD)    // 4160 padded window elems
#define TILE_S (WC * LPAD)       // 2048 padded tile slots

// Static scratch (no runtime allocation allowed)
__device__ float g_yn[MDIM * CTOT];
__device__ float g_rmax1[MDIM];  // per-row max of yn (pre-normalization)
__device__ float g_rmax2[MDIM];  // per-row max of X2 (pre-normalization)

// Deterministic block max (blockDim.x = 512 = 16 warps).
__device__ __forceinline__ float blockReduceMax(float v, float* sred) {
    __syncthreads();
    int lane = threadIdx.x & 31, wid = threadIdx.x >> 5;
    #pragma unroll
    for (int o = 16; o; o >>= 1) v = fmaxf(v, __shfl_xor_sync(0xffffffffu, v, o));
    if (lane == 0) sred[wid] = v;
    __syncthreads();
    if (wid == 0) {
        float x = (lane < 16) ? sred[lane] : -INFINITY;
        #pragma unroll
        for (int o = 16; o; o >>= 1) x = fmaxf(x, __shfl_xor_sync(0xffffffffu, x, o));
        if (lane == 0) sred[0] = x;
    }
    __syncthreads();
    return sred[0];
}

// ---------------------------------------------------------------------------
// Forward: one block per output row r; 8 column tiles of 64 output cols.
// Order of linear ops rearranged (they commute across axes):
//   row-resize -> lambda-conv(L) -> col-resize -> *H -> skew-sum -> row max
// ---------------------------------------------------------------------------
__global__ void __launch_bounds__(512) k_fwd(const float* __restrict__ X,
                                             const float* __restrict__ H) {
    __shared__ float sRow[SROW_N];   // row-combined window (130 x 32 padded)
    __shared__ float sLam[SROW_N];   // lambda-conv'd window
    __shared__ float sP[TILE_S];     // H * col-resized tile (64 x 32 padded)
    __shared__ float syn[CTOT];      // yn accumulator for this row
    __shared__ float sred[32];

    const int r = blockIdx.x, tid = threadIdx.x;
    const int l = tid & 31;          // lambda index (31 == padding lane)
    const int seg = tid >> 5;        // 0..15

    // Row-resize taps ([1/8,3/8,3/8,1/8], renormalized at edges)
    float w0, w1, w2, w3; int i0, i1, i2, i3;
    if (r == 0) {
        w0 = 0.f;     w1 = 3.f/7.f; w2 = 3.f/7.f; w3 = 1.f/7.f;
        i0 = 0; i1 = 0; i2 = 1; i3 = 2;
    } else if (r == MDIM - 1) {
        w0 = 1.f/7.f; w1 = 3.f/7.f; w2 = 3.f/7.f; w3 = 0.f;
        i0 = 2*r - 1; i1 = 2*r; i2 = 2*r + 1; i3 = i2;
    } else {
        w0 = 0.125f;  w1 = 0.375f;  w2 = 0.375f;  w3 = 0.125f;
        i0 = 2*r - 1; i1 = 2*r; i2 = 2*r + 1; i3 = 2*r + 2;
    }
    const float* X0 = X + (size_t)i0 * ROWE;
    const float* X1 = X + (size_t)i1 * ROWE;
    const float* X2p = X + (size_t)i2 * ROWE;
    const float* X3 = X + (size_t)i3 * ROWE;
    const float* Hr = H + (size_t)r * XCE;

    for (int cc = tid; cc < CTOT; cc += 512) syn[cc] = 0.f;

    for (int t = 0; t < NTILE; ++t) {
        const int c0 = t * WC;
        const int baseCol = 2 * c0 - 1;       // input col of window slot 0

        __syncthreads();                       // prior-tile consumers done

        // Phase A: row-combine 4 input rows into padded window.
        // warp-per-column: lanes 0..30 load 31 contiguous floats.
        for (int idx = tid; idx < SROW_N; idx += 512) {
            int col = idx >> 5, ll = idx & 31;
            int g = (baseCol + col) * LDIM + ll;
            if (ll < LDIM && g >= 0 && g < ROWE) {
                sRow[idx] = w0 * __ldg(X0 + g) + w1 * __ldg(X1 + g)
                          + w2 * __ldg(X2p + g) + w3 * __ldg(X3 + g);
            }
        }
        __syncthreads();

        // Phase A2: lambda conv [1/4,1/2,1/4] along l (zero pad at l=0,30).
        for (int idx = tid; idx < SROW_N; idx += 512) {
            int ll = idx & 31;
            if (ll < LDIM) {
                float v = 0.5f * sRow[idx];
                if (ll > 0)        v += 0.25f * sRow[idx - 1];
                if (ll < LDIM - 1) v += 0.25f * sRow[idx + 1];
                sLam[idx] = v;
            }
        }
        __syncthreads();

        // Phase B: 4-tap column resize of sLam, multiply by H -> sP.
        #pragma unroll
        for (int p = 0; p < 4; ++p) {
            int dc = p * 16 + seg;             // 0..63
            if (l < LDIM) {
                int c = c0 + dc;
                float v;
                if (c == 0) {
                    v = (3.f/7.f)*sLam[1*LPAD + l] + (3.f/7.f)*sLam[2*LPAD + l]
                      + (1.f/7.f)*sLam[3*LPAD + l];
                } else if (c == MDIM - 1) {
                    v = (1.f/7.f)*sLam[126*LPAD + l] + (3.f/7.f)*sLam[127*LPAD + l]
                      + (3.f/7.f)*sLam[128*LPAD + l];
                } else {
                    int b = 2 * dc * LPAD + l;
                    v = 0.125f*sLam[b]          + 0.375f*sLam[b + LPAD]
                      + 0.375f*sLam[b + 2*LPAD] + 0.125f*sLam[b + 3*LPAD];
                }
                sP[dc * LPAD + l] = __ldg(Hr + c * LDIM + l) * v;
            }
        }
        __syncthreads();

        // Phase D: skewed sum into yn accumulator (tile-private range)
        if (tid < WC + LDIM - 1) {             // 94 output positions
            int lcc = tid;
            int ilo = lcc - (WC - 1); if (ilo < 0) ilo = 0;
            int ihi = (lcc < LDIM - 1) ? lcc : (LDIM - 1);
            float acc = 0.f;
            for (int i = ilo; i <= ihi; ++i)
                acc += sP[(lcc - i) * LPAD + i];
            syn[c0 + lcc] += acc;
        }
    }
    __syncthreads();

    // Row max + write yn row
    float lmax = -INFINITY;
    float* ynr = g_yn + r * CTOT;
    for (int cc = tid; cc < CTOT; cc += 512) {
        float v = syn[cc];
        ynr[cc] = v;
        lmax = fmaxf(lmax, v);
    }
    float bm = blockReduceMax(lmax, sred);
    if (tid == 0) g_rmax1[r] = bm;
}

// ---------------------------------------------------------------------------
// Backward pass 1: per-row max of X2 only (H streams once, lands in L2).
// ---------------------------------------------------------------------------
__global__ void __launch_bounds__(512) k_bwd1(const float* __restrict__ y,
                                              const float* __restrict__ H) {
    __shared__ float srr[CTOT];
    __shared__ float sred[32];
    const int r = blockIdx.x, tid = threadIdx.x;
    const int l = tid & 31, seg = tid >> 5;

    float v0 = (tid < MDIM) ? g_rmax1[tid] : -INFINITY;
    const float invY = 1.0f / blockReduceMax(v0, sred);

    const float* ynr = g_yn + r * CTOT;
    const float* yr  = y + r * CTOT;
    for (int cc = tid; cc < CTOT; cc += 512)
        srr[cc] = ynr[cc] * invY - yr[cc];
    __syncthreads();

    const float* Hr = H + (size_t)r * XCE;
    float lmax = -INFINITY;
    if (l < LDIM) {
        for (int m = seg; m < MDIM; m += 16) {
            int c = m + l;
            float v = 0.5f * srr[c];
            if (l > 0)        v += 0.25f * srr[c - 1];
            if (l < LDIM - 1) v += 0.25f * srr[c + 1];
            lmax = fmaxf(lmax, __ldg(Hr + m * LDIM + l) * v);
        }
    }
    float bm = blockReduceMax(lmax, sred);
    if (tid == 0) g_rmax2[r] = bm;
}

// ---------------------------------------------------------------------------
// Backward pass 2: recompute X2 (H now L2-resident), write normalized output.
// ---------------------------------------------------------------------------
__global__ void __launch_bounds__(512) k_bwd2(const float* __restrict__ y,
                                              const float* __restrict__ H,
                                              float* __restrict__ out) {
    __shared__ float srr[CTOT];
    __shared__ float sred[32];
    const int r = blockIdx.x, tid = threadIdx.x;
    const int l = tid & 31, seg = tid >> 5;

    float v0 = (tid < MDIM) ? g_rmax1[tid] : -INFINITY;
    const float invY = 1.0f / blockReduceMax(v0, sred);
    float v1 = (tid < MDIM) ? g_rmax2[tid] : -INFINITY;
    const float invO = 1.0f / blockReduceMax(v1, sred);

    const float* ynr = g_yn + r * CTOT;
    const float* yr  = y + r * CTOT;
    for (int cc = tid; cc < CTOT; cc += 512)
        srr[cc] = ynr[cc] * invY - yr[cc];
    __syncthreads();

    const float* Hr   = H   + (size_t)r * XCE;
    float*       outr = out + (size_t)r * XCE;
    if (l < LDIM) {
        for (int m = seg; m < MDIM; m += 16) {
            int c = m + l;
            float v = 0.5f * srr[c];
            if (l > 0)        v += 0.25f * srr[c - 1];
            if (l < LDIM - 1) v += 0.25f * srr[c + 1];
            outr[m * LDIM + l] = (__ldg(Hr + m * LDIM + l) * v) * invO;
        }
    }
}

extern "C" void kernel_launch(void* const* d_in, const int* in_sizes, int n_in,
                              void* d_out, int out_size) {
    // Identify inputs by element count; fall back to metadata order.
    const float *X = 0, *y = 0, *H = 0;
    for (int i = 0; i < n_in; ++i) {
        if      (in_sizes[i] == NX * NX * LDIM)     X = (const float*)d_in[i];
        else if (in_sizes[i] == MDIM * CTOT)        y = (const float*)d_in[i];
        else if (in_sizes[i] == MDIM * MDIM * LDIM) H = (const float*)d_in[i];
    }
    if (!X || !y || !H) {
        X = (const float*)d_in[0];
        y = (const float*)d_in[1];
        H = (const float*)d_in[2];
    }
    float* out = (float*)d_out;

    k_fwd <<<MDIM, 512>>>(X, H);
    k_bwd1<<<MDIM, 512>>>(y, H);
    k_bwd2<<<MDIM, 512>>>(y, H, out);
}

// round 7
// speedup vs baseline: 2.0565x; 2.0565x over previous
#include <cuda_runtime.h>
#include <math.h>

#define MDIM 512
#define LDIM 31
#define CTOT 542                 // MDIM + LDIM - 1
#define NX   1024
#define ROWE (NX * LDIM)         // 31744 floats per input row strip
#define XCE  (MDIM * LDIM)       // 15872 floats per H/out row strip

#define WC     64                // output columns per tile
#define NTILE  (MDIM / WC)       // 8
#define WCOLS  (2 * WC + 2)      // 130 input cols per window
#define YLEN   94                // outputs per tile (WC + LDIM - 1)
#define YPAD   96

// Static scratch
__device__ float g_ynp[NTILE * MDIM * YPAD]; // per-tile partial yn
__device__ float g_yn[MDIM * CTOT];
__device__ float g_rmax1[MDIM];
__device__ float g_rmax2[MDIM];

__device__ __forceinline__ float blockReduceMax(float v, float* sred) {
    __syncthreads();
    int lane = threadIdx.x & 31, wid = threadIdx.x >> 5;
    int nw = blockDim.x >> 5;
    #pragma unroll
    for (int o = 16; o; o >>= 1) v = fmaxf(v, __shfl_xor_sync(0xffffffffu, v, o));
    if (lane == 0) sred[wid] = v;
    __syncthreads();
    if (wid == 0) {
        float x = (lane < nw) ? sred[lane] : -INFINITY;
        #pragma unroll
        for (int o = 16; o; o >>= 1) x = fmaxf(x, __shfl_xor_sync(0xffffffffu, x, o));
        if (lane == 0) sred[0] = x;
    }
    __syncthreads();
    return sred[0];
}

// ---------------------------------------------------------------------------
// Forward: one block per (tile, row). 256 threads, straight-line, 2 barriers.
// Math order (linear ops commute): row-resize -> lambda(L) -> col-resize -> *H
// ---------------------------------------------------------------------------
__global__ void __launch_bounds__(256, 6) k_fwd(const float* __restrict__ X,
                                                const float* __restrict__ H) {
    __shared__ float sLam[WCOLS * 32];   // 130 x 32 = 16.25 KB
    __shared__ float sP[WC * 33];        // 64 x 33 = 8.25 KB (conflict-free skew)

    const int t = blockIdx.x, r = blockIdx.y;
    const int tid = threadIdx.x;
    const int lane = tid & 31, warp = tid >> 5;     // 8 warps
    const int c0 = t * WC;
    const int baseCol = 2 * c0 - 1;

    // Row-resize taps ([1/8,3/8,3/8,1/8], renormalized at edges)
    float w0, w1, w2, w3; int i0, i1, i2, i3;
    if (r == 0) {
        w0 = 0.f;     w1 = 3.f/7.f; w2 = 3.f/7.f; w3 = 1.f/7.f;
        i0 = 0; i1 = 0; i2 = 1; i3 = 2;
    } else if (r == MDIM - 1) {
        w0 = 1.f/7.f; w1 = 3.f/7.f; w2 = 3.f/7.f; w3 = 0.f;
        i0 = 2*r - 1; i1 = 2*r; i2 = 2*r + 1; i3 = i2;
    } else {
        w0 = 0.125f;  w1 = 0.375f;  w2 = 0.375f;  w3 = 0.125f;
        i0 = 2*r - 1; i1 = 2*r; i2 = 2*r + 1; i3 = 2*r + 2;
    }
    const float* X0 = X + (size_t)i0 * ROWE;
    const float* X1 = X + (size_t)i1 * ROWE;
    const float* X2p = X + (size_t)i2 * ROWE;
    const float* X3 = X + (size_t)i3 * ROWE;
    const float* Hr = H + (size_t)r * XCE;

    // Phase A: row-combine + lambda-conv via warp shuffles (lane = lambda idx).
    for (int col = warp; col < WCOLS; col += 8) {
        int ic = baseCol + col;
        float x = 0.f;
        if (lane < LDIM && ic >= 0 && ic < NX) {
            int g = ic * LDIM + lane;
            x = w0 * __ldg(X0 + g) + w1 * __ldg(X1 + g)
              + w2 * __ldg(X2p + g) + w3 * __ldg(X3 + g);
        }
        float xm = __shfl_up_sync(0xffffffffu, x, 1);
        float xp = __shfl_down_sync(0xffffffffu, x, 1);
        float v = 0.5f * x;
        if (lane > 0)         v += 0.25f * xm;
        if (lane < LDIM - 1)  v += 0.25f * xp;
        sLam[col * 32 + lane] = v;           // lane 31 stores dead pad
    }
    __syncthreads();

    // Phase B: 4-tap column resize + H multiply -> sP (stride 33).
    {
        const int l = lane, dc0 = warp;
        if (l < LDIM) {
            #pragma unroll
            for (int q = 0; q < 8; ++q) {
                int dc = dc0 + q * 8;            // 0..63
                int c = c0 + dc;
                float v;
                if (c == 0) {
                    v = (3.f/7.f)*sLam[1*32 + l] + (3.f/7.f)*sLam[2*32 + l]
                      + (1.f/7.f)*sLam[3*32 + l];
                } else if (c == MDIM - 1) {
                    v = (1.f/7.f)*sLam[126*32 + l] + (3.f/7.f)*sLam[127*32 + l]
                      + (3.f/7.f)*sLam[128*32 + l];
                } else {
                    int b = 2 * dc * 32 + l;
                    v = 0.125f*sLam[b]      + 0.375f*sLam[b + 32]
                      + 0.375f*sLam[b + 64] + 0.125f*sLam[b + 96];
                }
                sP[dc * 33 + l] = __ldg(Hr + c * LDIM + l) * v;
            }
        }
    }
    __syncthreads();

    // Phase D: skewed partial sums for this tile (deterministic, no atomics).
    if (tid < YLEN) {
        int lcc = tid;
        int ilo = lcc - (WC - 1); if (ilo < 0) ilo = 0;
        int ihi = (lcc < LDIM - 1) ? lcc : (LDIM - 1);
        float acc = 0.f;
        for (int i = ilo; i <= ihi; ++i)
            acc += sP[(lcc - i) * 33 + i];     // bank-conflict-free (stride 33)
        g_ynp[(t * MDIM + r) * YPAD + lcc] = acc;
    }
}

// ---------------------------------------------------------------------------
// Combine tile partials -> yn row + per-row max.
// ---------------------------------------------------------------------------
__global__ void __launch_bounds__(256) k_max(void) {
    __shared__ float sred[32];
    const int r = blockIdx.x, tid = threadIdx.x;
    float lmax = -INFINITY;
    for (int cc = tid; cc < CTOT; cc += 256) {
        int thi = cc >> 6; if (thi > NTILE - 1) thi = NTILE - 1;
        int tlo = (cc - 30) / 64; if (tlo < 0) tlo = 0;   // = max(0, ceil((cc-93)/64))
        float s = 0.f;
        for (int t2 = tlo; t2 <= thi; ++t2)
            s += g_ynp[(t2 * MDIM + r) * YPAD + (cc - (t2 << 6))];
        g_yn[r * CTOT + cc] = s;
        lmax = fmaxf(lmax, s);
    }
    float bm = blockReduceMax(lmax, sred);
    if (tid == 0) g_rmax1[r] = bm;
}

// ---------------------------------------------------------------------------
// Backward pass 1: per-row max of X2 (H streams once, lands in L2).
// ---------------------------------------------------------------------------
__global__ void __launch_bounds__(512) k_bwd1(const float* __restrict__ y,
                                              const float* __restrict__ H) {
    __shared__ float srr[CTOT];
    __shared__ float sred[32];
    const int r = blockIdx.x, tid = threadIdx.x;
    const int l = tid & 31, seg = tid >> 5;

    float v0 = (tid < MDIM) ? g_rmax1[tid] : -INFINITY;
    const float invY = 1.0f / blockReduceMax(v0, sred);

    const float* ynr = g_yn + r * CTOT;
    const float* yr  = y + r * CTOT;
    for (int cc = tid; cc < CTOT; cc += 512)
        srr[cc] = ynr[cc] * invY - yr[cc];
    __syncthreads();

    const float* Hr = H + (size_t)r * XCE;
    float lmax = -INFINITY;
    if (l < LDIM) {
        for (int m = seg; m < MDIM; m += 16) {
            int c = m + l;
            float v = 0.5f * srr[c];
            if (l > 0)        v += 0.25f * srr[c - 1];
            if (l < LDIM - 1) v += 0.25f * srr[c + 1];
            lmax = fmaxf(lmax, __ldg(Hr + m * LDIM + l) * v);
        }
    }
    float bm = blockReduceMax(lmax, sred);
    if (tid == 0) g_rmax2[r] = bm;
}

// ---------------------------------------------------------------------------
// Backward pass 2: recompute X2 (H L2-resident), write normalized output.
// ---------------------------------------------------------------------------
__global__ void __launch_bounds__(512) k_bwd2(const float* __restrict__ y,
                                              const float* __restrict__ H,
                                              float* __restrict__ out) {
    __shared__ float srr[CTOT];
    __shared__ float sred[32];
    const int r = blockIdx.x, tid = threadIdx.x;
    const int l = tid & 31, seg = tid >> 5;

    float v0 = (tid < MDIM) ? g_rmax1[tid] : -INFINITY;
    const float invY = 1.0f / blockReduceMax(v0, sred);
    float v1 = (tid < MDIM) ? g_rmax2[tid] : -INFINITY;
    const float invO = 1.0f / blockReduceMax(v1, sred);

    const float* ynr = g_yn + r * CTOT;
    const float* yr  = y + r * CTOT;
    for (int cc = tid; cc < CTOT; cc += 512)
        srr[cc] = ynr[cc] * invY - yr[cc];
    __syncthreads();

    const float* Hr   = H   + (size_t)r * XCE;
    float*       outr = out + (size_t)r * XCE;
    if (l < LDIM) {
        for (int m = seg; m < MDIM; m += 16) {
            int c = m + l;
            float v = 0.5f * srr[c];
            if (l > 0)        v += 0.25f * srr[c - 1];
            if (l < LDIM - 1) v += 0.25f * srr[c + 1];
            outr[m * LDIM + l] = (__ldg(Hr + m * LDIM + l) * v) * invO;
        }
    }
}

extern "C" void kernel_launch(void* const* d_in, const int* in_sizes, int n_in,
                              void* d_out, int out_size) {
    const float *X = 0, *y = 0, *H = 0;
    for (int i = 0; i < n_in; ++i) {
        if      (in_sizes[i] == NX * NX * LDIM)     X = (const float*)d_in[i];
        else if (in_sizes[i] == MDIM * CTOT)        y = (const float*)d_in[i];
        else if (in_sizes[i] == MDIM * MDIM * LDIM) H = (const float*)d_in[i];
    }
    if (!X || !y || !H) {
        X = (const float*)d_in[0];
        y = (const float*)d_in[1];
        H = (const float*)d_in[2];
    }
    float* out = (float*)d_out;

    dim3 gf(NTILE, MDIM);
    k_fwd <<<gf, 256>>>(X, H);
    k_max <<<MDIM, 256>>>();
    k_bwd1<<<MDIM, 512>>>(y, H);
    k_bwd2<<<MDIM, 512>>>(y, H, out);
}

// round 8
// speedup vs baseline: 2.3237x; 1.1300x over previous
#include <cuda_runtime.h>
#include <math.h>

#define MDIM 512
#define LDIM 31
#define CTOT 542                 // MDIM + LDIM - 1
#define NX   1024
#define ROWE (NX * LDIM)         // 31744 floats per input row strip
#define XCE  (MDIM * LDIM)       // 15872 floats per H/out row strip
#define XC4  (XCE / 4)           // 3968 float4 per row

#define WC     64                // output columns per tile
#define NTILE  (MDIM / WC)       // 8
#define WCOLS  (2 * WC + 2)      // 130 input cols per window
#define YLEN   94                // outputs per tile (WC + LDIM - 1)
#define YPAD   96

// Static scratch
__device__ float g_ynp[NTILE * MDIM * YPAD]; // per-tile partial yn
__device__ float g_yn[MDIM * CTOT];
__device__ float g_rmax1[MDIM];
__device__ float g_rmax2[MDIM];

__device__ __forceinline__ float blockReduceMax(float v, float* sred) {
    __syncthreads();
    int lane = threadIdx.x & 31, wid = threadIdx.x >> 5;
    int nw = blockDim.x >> 5;
    #pragma unroll
    for (int o = 16; o; o >>= 1) v = fmaxf(v, __shfl_xor_sync(0xffffffffu, v, o));
    if (lane == 0) sred[wid] = v;
    __syncthreads();
    if (wid == 0) {
        float x = (lane < nw) ? sred[lane] : -INFINITY;
        #pragma unroll
        for (int o = 16; o; o >>= 1) x = fmaxf(x, __shfl_xor_sync(0xffffffffu, x, o));
        if (lane == 0) sred[0] = x;
    }
    __syncthreads();
    return sred[0];
}

// ---------------------------------------------------------------------------
// Forward: one block per (tile, row). 256 threads, straight-line, 2 barriers.
// Math order (linear ops commute): row-resize -> lambda(L) -> col-resize -> *H
// ---------------------------------------------------------------------------
__global__ void __launch_bounds__(256, 6) k_fwd(const float* __restrict__ X,
                                                const float* __restrict__ H) {
    __shared__ float sLam[WCOLS * 32];   // 130 x 32 = 16.25 KB
    __shared__ float sP[WC * 33];        // 64 x 33 = 8.25 KB (conflict-free skew)

    const int t = blockIdx.x, r = blockIdx.y;
    const int tid = threadIdx.x;
    const int lane = tid & 31, warp = tid >> 5;     // 8 warps
    const int c0 = t * WC;
    const int baseCol = 2 * c0 - 1;

    // Row-resize taps ([1/8,3/8,3/8,1/8], renormalized at edges)
    float w0, w1, w2, w3; int i0, i1, i2, i3;
    if (r == 0) {
        w0 = 0.f;     w1 = 3.f/7.f; w2 = 3.f/7.f; w3 = 1.f/7.f;
        i0 = 0; i1 = 0; i2 = 1; i3 = 2;
    } else if (r == MDIM - 1) {
        w0 = 1.f/7.f; w1 = 3.f/7.f; w2 = 3.f/7.f; w3 = 0.f;
        i0 = 2*r - 1; i1 = 2*r; i2 = 2*r + 1; i3 = i2;
    } else {
        w0 = 0.125f;  w1 = 0.375f;  w2 = 0.375f;  w3 = 0.125f;
        i0 = 2*r - 1; i1 = 2*r; i2 = 2*r + 1; i3 = 2*r + 2;
    }
    const float* X0 = X + (size_t)i0 * ROWE;
    const float* X1 = X + (size_t)i1 * ROWE;
    const float* X2p = X + (size_t)i2 * ROWE;
    const float* X3 = X + (size_t)i3 * ROWE;
    const float* Hr = H + (size_t)r * XCE;

    // Phase A: row-combine + lambda-conv via warp shuffles (lane = lambda idx).
    for (int col = warp; col < WCOLS; col += 8) {
        int ic = baseCol + col;
        float x = 0.f;
        if (lane < LDIM && ic >= 0 && ic < NX) {
            int g = ic * LDIM + lane;
            x = w0 * __ldg(X0 + g) + w1 * __ldg(X1 + g)
              + w2 * __ldg(X2p + g) + w3 * __ldg(X3 + g);
        }
        float xm = __shfl_up_sync(0xffffffffu, x, 1);
        float xp = __shfl_down_sync(0xffffffffu, x, 1);
        float v = 0.5f * x;
        if (lane > 0)         v += 0.25f * xm;
        if (lane < LDIM - 1)  v += 0.25f * xp;
        sLam[col * 32 + lane] = v;           // lane 31 stores dead pad
    }
    __syncthreads();

    // Phase B: 4-tap column resize + H multiply -> sP (stride 33).
    {
        const int l = lane, dc0 = warp;
        if (l < LDIM) {
            #pragma unroll
            for (int q = 0; q < 8; ++q) {
                int dc = dc0 + q * 8;            // 0..63
                int c = c0 + dc;
                float v;
                if (c == 0) {
                    v = (3.f/7.f)*sLam[1*32 + l] + (3.f/7.f)*sLam[2*32 + l]
                      + (1.f/7.f)*sLam[3*32 + l];
                } else if (c == MDIM - 1) {
                    v = (1.f/7.f)*sLam[126*32 + l] + (3.f/7.f)*sLam[127*32 + l]
                      + (3.f/7.f)*sLam[128*32 + l];
                } else {
                    int b = 2 * dc * 32 + l;
                    v = 0.125f*sLam[b]      + 0.375f*sLam[b + 32]
                      + 0.375f*sLam[b + 64] + 0.125f*sLam[b + 96];
                }
                sP[dc * 33 + l] = __ldg(Hr + c * LDIM + l) * v;
            }
        }
    }
    __syncthreads();

    // Phase D: skewed partial sums for this tile (deterministic, no atomics).
    if (tid < YLEN) {
        int lcc = tid;
        int ilo = lcc - (WC - 1); if (ilo < 0) ilo = 0;
        int ihi = (lcc < LDIM - 1) ? lcc : (LDIM - 1);
        float acc = 0.f;
        for (int i = ilo; i <= ihi; ++i)
            acc += sP[(lcc - i) * 33 + i];     // bank-conflict-free (stride 33)
        g_ynp[(t * MDIM + r) * YPAD + lcc] = acc;
    }
}

// ---------------------------------------------------------------------------
// Combine tile partials -> yn row + per-row max.
// ---------------------------------------------------------------------------
__global__ void __launch_bounds__(256) k_max(void) {
    __shared__ float sred[32];
    const int r = blockIdx.x, tid = threadIdx.x;
    float lmax = -INFINITY;
    for (int cc = tid; cc < CTOT; cc += 256) {
        int thi = cc >> 6; if (thi > NTILE - 1) thi = NTILE - 1;
        int tlo = (cc - 30) / 64; if (tlo < 0) tlo = 0;   // = max(0, ceil((cc-93)/64))
        float s = 0.f;
        for (int t2 = tlo; t2 <= thi; ++t2)
            s += g_ynp[(t2 * MDIM + r) * YPAD + (cc - (t2 << 6))];
        g_yn[r * CTOT + cc] = s;
        lmax = fmaxf(lmax, s);
    }
    float bm = blockReduceMax(lmax, sred);
    if (tid == 0) g_rmax1[r] = bm;
}

// Build srr (residual) and its full lambda-conv s2 (zero-extended ends).
__device__ __forceinline__ void buildResidual(const float* __restrict__ y, int r,
                                              float invY, float* srr, float* s2) {
    const float* ynr = g_yn + r * CTOT;
    const float* yr  = y + r * CTOT;
    const int tid = threadIdx.x, nt = blockDim.x;
    for (int cc = tid; cc < CTOT; cc += nt)
        srr[cc] = ynr[cc] * invY - yr[cc];
    __syncthreads();
    for (int cc = tid; cc < CTOT; cc += nt) {
        float a = (cc > 0)        ? srr[cc - 1] : 0.f;
        float b = (cc < CTOT - 1) ? srr[cc + 1] : 0.f;
        s2[cc] = 0.25f * (a + b) + 0.5f * srr[cc];
    }
    __syncthreads();
}

// X2 element from precomputed s2 with boundary corrections.
//   i in (0,30): v = s2[m+i]
//   i==0:  v = s2[m]    - 0.25*srr[m-1]   (term absent when m==0)
//   i==30: v = s2[m+30] - 0.25*srr[m+31]  (term absent when m==511)
__device__ __forceinline__ float x2val(const float* srr, const float* s2,
                                       int m, int i) {
    float v = s2[m + i];
    if (i == 0  && m > 0)        v -= 0.25f * srr[m - 1];
    if (i == 30 && m < MDIM - 1) v -= 0.25f * srr[m + 31];
    return v;
}

// ---------------------------------------------------------------------------
// Backward pass 1: per-row max of X2 (float4-streamed H; H lands in L2).
// ---------------------------------------------------------------------------
__global__ void __launch_bounds__(512) k_bwd1(const float* __restrict__ y,
                                              const float* __restrict__ H) {
    __shared__ float srr[CTOT];
    __shared__ float s2[CTOT];
    __shared__ float sred[32];
    const int r = blockIdx.x, tid = threadIdx.x;

    float v0 = (tid < MDIM) ? g_rmax1[tid] : -INFINITY;
    const float invY = 1.0f / blockReduceMax(v0, sred);
    buildResidual(y, r, invY, srr, s2);

    const float4* H4 = (const float4*)(H + (size_t)r * XCE);
    float lmax = -INFINITY;
    for (int j = tid; j < XC4; j += 512) {
        float4 h = __ldg(H4 + j);
        int e = j * 4;
        int m = e / LDIM, i = e - m * LDIM;
        float a0 = h.x * x2val(srr, s2, m, i);
        if (++i == LDIM) { i = 0; ++m; }
        float a1 = h.y * x2val(srr, s2, m, i);
        if (++i == LDIM) { i = 0; ++m; }
        float a2 = h.z * x2val(srr, s2, m, i);
        if (++i == LDIM) { i = 0; ++m; }
        float a3 = h.w * x2val(srr, s2, m, i);
        lmax = fmaxf(fmaxf(fmaxf(a0, a1), fmaxf(a2, a3)), lmax);
    }
    float bm = blockReduceMax(lmax, sred);
    if (tid == 0) g_rmax2[r] = bm;
}

// ---------------------------------------------------------------------------
// Backward pass 2: recompute X2 (H L2-resident), write normalized output.
// ---------------------------------------------------------------------------
__global__ void __launch_bounds__(512) k_bwd2(const float* __restrict__ y,
                                              const float* __restrict__ H,
                                              float* __restrict__ out) {
    __shared__ float srr[CTOT];
    __shared__ float s2[CTOT];
    __shared__ float sred[32];
    const int r = blockIdx.x, tid = threadIdx.x;

    float v0 = (tid < MDIM) ? g_rmax1[tid] : -INFINITY;
    const float invY = 1.0f / blockReduceMax(v0, sred);
    float v1 = (tid < MDIM) ? g_rmax2[tid] : -INFINITY;
    const float invO = 1.0f / blockReduceMax(v1, sred);
    buildResidual(y, r, invY, srr, s2);

    const float4* H4 = (const float4*)(H + (size_t)r * XCE);
    float4*       O4 = (float4*)(out + (size_t)r * XCE);
    for (int j = tid; j < XC4; j += 512) {
        float4 h = __ldg(H4 + j);
        int e = j * 4;
        int m = e / LDIM, i = e - m * LDIM;
        float4 o;
        o.x = h.x * x2val(srr, s2, m, i) * invO;
        if (++i == LDIM) { i = 0; ++m; }
        o.y = h.y * x2val(srr, s2, m, i) * invO;
        if (++i == LDIM) { i = 0; ++m; }
        o.z = h.z * x2val(srr, s2, m, i) * invO;
        if (++i == LDIM) { i = 0; ++m; }
        o.w = h.w * x2val(srr, s2, m, i) * invO;
        O4[j] = o;
    }
}

extern "C" void kernel_launch(void* const* d_in, const int* in_sizes, int n_in,
                              void* d_out, int out_size) {
    const float *X = 0, *y = 0, *H = 0;
    for (int i = 0; i < n_in; ++i) {
        if      (in_sizes[i] == NX * NX * LDIM)     X = (const float*)d_in[i];
        else if (in_sizes[i] == MDIM * CTOT)        y = (const float*)d_in[i];
        else if (in_sizes[i] == MDIM * MDIM * LDIM) H = (const float*)d_in[i];
    }
    if (!X || !y || !H) {
        X = (const float*)d_in[0];
        y = (const float*)d_in[1];
        H = (const float*)d_in[2];
    }
    float* out = (float*)d_out;

    dim3 gf(NTILE, MDIM);
    k_fwd <<<gf, 256>>>(X, H);
    k_max <<<MDIM, 256>>>();
    k_bwd1<<<MDIM, 512>>>(y, H);
    k_bwd2<<<MDIM, 512>>>(y, H, out);
}